// round 15
// baseline (speedup 1.0000x reference)
#include <cuda_runtime.h>
#include <cuda_fp16.h>
#include <cstdint>
#include <math_constants.h>

#define NN   50000
#define EE   1600000
#define ETOT (EE + NN)
#define HC   128
#define NH   2
#define NEG  0.2f
#define EPSV 1e-5f

#define GEMM_BLOCKS ((NN + 63) / 64)    // 782
#define SCAN_BLOCKS ((NN + 255) / 256)  // 196

// ---------------- scratch (device globals; no runtime allocation) ----------
__device__ __half2  g_xlh[(size_t)NN * 64];     // x @ W_l in fp16 (12.8 MB)
__device__ float    g_xr[(size_t)NN * HC];      // x @ W_r   (25.6 MB)
__device__ int      g_esrc[ETOT];               // CSR src array (6.6 MB)
__device__ int      g_deg[NN];
__device__ int      g_off[NN + 1];
__device__ int      g_cursor[NN];
__device__ int      g_bsum[SCAN_BLOCKS];
__device__ int      g_bsumx[SCAN_BLOCKS];
__device__ float    g_chs1[HC];
__device__ float    g_chs2[HC];
__device__ float    g_nsc[HC];                  // norm scale
__device__ float    g_nsh[HC];                  // norm shift
__device__ int      g_is64;

// ---------------- helpers ---------------------------------------------------
__device__ __forceinline__ void load_edge(const void* ei, int e, int& src, int& dst) {
    if (e >= EE) { src = dst = e - EE; return; }
    if (g_is64) {
        const long long* p = (const long long*)ei;
        src = (int)p[e]; dst = (int)p[EE + e];
    } else {
        const int* p = (const int*)ei;
        src = p[e]; dst = p[EE + e];
    }
}

__device__ __forceinline__ void tf32split(float v, uint32_t& hi, uint32_t& lo) {
    uint32_t h;
    asm("cvt.rna.tf32.f32 %0, %1;" : "=r"(h) : "f"(v));
    float l = v - __uint_as_float(h);
    uint32_t lr;
    asm("cvt.rna.tf32.f32 %0, %1;" : "=r"(lr) : "f"(l));
    hi = h; lo = lr;
}

__device__ __forceinline__ void mma8(float c[4], uint32_t a0, uint32_t a1,
                                     uint32_t a2, uint32_t a3,
                                     uint32_t b0, uint32_t b1) {
    asm volatile(
        "mma.sync.aligned.m16n8k8.row.col.f32.tf32.tf32.f32 "
        "{%0,%1,%2,%3}, {%4,%5,%6,%7}, {%8,%9}, {%0,%1,%2,%3};"
        : "+f"(c[0]), "+f"(c[1]), "+f"(c[2]), "+f"(c[3])
        : "r"(a0), "r"(a1), "r"(a2), "r"(a3), "r"(b0), "r"(b1));
}

__device__ __forceinline__ int block_scan_incl(int v, int t) {
    __shared__ int sw[8];
    int lane = t & 31, warp = t >> 5;
    #pragma unroll
    for (int off = 1; off < 32; off <<= 1) {
        int u = __shfl_up_sync(0xffffffffu, v, off);
        if (lane >= off) v += u;
    }
    if (lane == 31) sw[warp] = v;
    __syncthreads();
    if (warp == 0) {
        int wv = (lane < 8) ? sw[lane] : 0;
        #pragma unroll
        for (int off = 1; off < 8; off <<= 1) {
            int u = __shfl_up_sync(0xffffffffu, wv, off);
            if (lane >= off) wv += u;
        }
        if (lane < 8) sw[lane] = wv;
    }
    __syncthreads();
    if (warp > 0) v += sw[warp - 1];
    return v;
}

// ---------------- kernels ----------------------------------------------------

__global__ void k_detect(const void* ei) {
    if (threadIdx.x == 0) {
        const int* p = (const int*)ei;
        int is64 = 1;
        #pragma unroll 1
        for (int i = 0; i < 64; i++)
            if (p[2 * i + 1] != 0) { is64 = 0; break; }
        g_is64 = is64;
    }
}

__global__ void k_zero(void) {
    int i = blockIdx.x * blockDim.x + threadIdx.x;
    if (i < NN) g_deg[i] = 0;
    if (i < HC) { g_chs1[i] = 0.0f; g_chs2[i] = 0.0f; }
}

// Tensor-core GEMM (3xTF32 split), B pre-split into smem (no cvt in inner
// loop), fused degree histogram tail.
__global__ __launch_bounds__(128) void k_gemm(const float* __restrict__ x,
                                              const float* __restrict__ Wl,
                                              const float* __restrict__ Wr,
                                              const void* __restrict__ ei) {
    __shared__ float    xs[64][132];
    __shared__ uint32_t wsh[16][132];
    __shared__ uint32_t wsl[16][132];
    const int node0 = blockIdx.x * 64;
    const int t = threadIdx.x;
    const int warp = t >> 5, lane = t & 31;
    const int gid = lane >> 2, tig = lane & 3;
    const int m0 = warp * 16;

    const float4* x4 = (const float4*)x;
    #pragma unroll
    for (int i = 0; i < 16; i++) {
        int lin = t + i * 128;
        int row = lin >> 5, c4 = lin & 31;
        int node = node0 + row;
        float4 v = (node < NN) ? x4[(size_t)node * 32 + c4]
                               : make_float4(0.f, 0.f, 0.f, 0.f);
        *(float4*)&xs[row][c4 * 4] = v;
    }

    const float* Wmat[2] = { Wl, Wr };

    #pragma unroll 1
    for (int g = 0; g < 2; g++) {
        const float* W = Wmat[g];
        float c[16][4];
        #pragma unroll
        for (int nt = 0; nt < 16; nt++)
            c[nt][0] = c[nt][1] = c[nt][2] = c[nt][3] = 0.0f;

        #pragma unroll 1
        for (int kc = 0; kc < 128; kc += 16) {
            __syncthreads();
            // load + pre-split W chunk [16][128]
            #pragma unroll
            for (int i = 0; i < 4; i++) {
                int lin = t + i * 128;
                int row = lin >> 5, c4 = lin & 31;
                float4 v = *(const float4*)&W[(size_t)(kc + row) * 128 + c4 * 4];
                uint32_t h0, l0, h1, l1, h2, l2, h3, l3;
                tf32split(v.x, h0, l0); tf32split(v.y, h1, l1);
                tf32split(v.z, h2, l2); tf32split(v.w, h3, l3);
                wsh[row][c4 * 4 + 0] = h0; wsl[row][c4 * 4 + 0] = l0;
                wsh[row][c4 * 4 + 1] = h1; wsl[row][c4 * 4 + 1] = l1;
                wsh[row][c4 * 4 + 2] = h2; wsl[row][c4 * 4 + 2] = l2;
                wsh[row][c4 * 4 + 3] = h3; wsl[row][c4 * 4 + 3] = l3;
            }
            __syncthreads();

            #pragma unroll
            for (int ks = 0; ks < 2; ks++) {
                int kk = ks * 8;
                float a0 = xs[m0 + gid][kc + kk + tig];
                float a1 = xs[m0 + gid + 8][kc + kk + tig];
                float a2 = xs[m0 + gid][kc + kk + tig + 4];
                float a3 = xs[m0 + gid + 8][kc + kk + tig + 4];
                uint32_t ah0, al0, ah1, al1, ah2, al2, ah3, al3;
                tf32split(a0, ah0, al0);
                tf32split(a1, ah1, al1);
                tf32split(a2, ah2, al2);
                tf32split(a3, al3 = 0, al3);  // placeholder avoided below
                tf32split(a3, ah3, al3);
                #pragma unroll
                for (int nt = 0; nt < 16; nt++) {
                    int n0 = nt * 8;
                    uint32_t bh0 = wsh[kk + tig][n0 + gid];
                    uint32_t bh1 = wsh[kk + tig + 4][n0 + gid];
                    uint32_t bl0 = wsl[kk + tig][n0 + gid];
                    uint32_t bl1 = wsl[kk + tig + 4][n0 + gid];
                    mma8(c[nt], ah0, ah1, ah2, ah3, bh0, bh1);
                    mma8(c[nt], ah0, ah1, ah2, ah3, bl0, bl1);
                    mma8(c[nt], al0, al1, al2, al3, bh0, bh1);
                }
            }
        }
        int r0 = node0 + m0 + gid;
        int r1 = r0 + 8;
        if (g == 0) {
            #pragma unroll
            for (int nt = 0; nt < 16; nt++) {
                int h2 = (nt * 8 + tig * 2) >> 1;
                if (r0 < NN) g_xlh[(size_t)r0 * 64 + h2] = __floats2half2_rn(c[nt][0], c[nt][1]);
                if (r1 < NN) g_xlh[(size_t)r1 * 64 + h2] = __floats2half2_rn(c[nt][2], c[nt][3]);
            }
        } else {
            #pragma unroll
            for (int nt = 0; nt < 16; nt++) {
                int col = nt * 8 + tig * 2;
                if (r0 < NN) *(float2*)&g_xr[(size_t)r0 * HC + col] = make_float2(c[nt][0], c[nt][1]);
                if (r1 < NN) *(float2*)&g_xr[(size_t)r1 * HC + col] = make_float2(c[nt][2], c[nt][3]);
            }
        }
        __syncthreads();
    }

    // ---- fused degree histogram tail ----
    const int EPB = (ETOT + GEMM_BLOCKS - 1) / GEMM_BLOCKS;
    int e0 = blockIdx.x * EPB;
    int e1 = min(e0 + EPB, ETOT);
    for (int e = e0 + t; e < e1; e += 128) {
        int src, dst;
        load_edge(ei, e, src, dst);
        (void)src;
        atomicAdd(&g_deg[dst], 1);
    }
}

// scan phase 1/2/3: device-wide exclusive scan of degrees
__global__ __launch_bounds__(256) void k_scan1(void) {
    int i = blockIdx.x * 256 + threadIdx.x;
    int d = (i < NN) ? g_deg[i] : 0;
    int incl = block_scan_incl(d, threadIdx.x);
    if (threadIdx.x == 255) g_bsum[blockIdx.x] = incl;
    g_off[min(i, NN)] = incl - d;
}
__global__ __launch_bounds__(256) void k_scan2(void) {
    int t = threadIdx.x;
    int v = (t < SCAN_BLOCKS) ? g_bsum[t] : 0;
    int incl = block_scan_incl(v, t);
    if (t < SCAN_BLOCKS) g_bsumx[t] = incl - v;
    if (t == SCAN_BLOCKS - 1) g_off[NN] = incl;
}
__global__ __launch_bounds__(256) void k_scan3(void) {
    int i = blockIdx.x * 256 + threadIdx.x;
    if (i < NN) {
        int o = g_off[i] + g_bsumx[blockIdx.x];
        g_off[i] = o;
        g_cursor[i] = o;
    }
}

// CSR scatter: srcs grouped by dst (4 edges/thread)
__global__ __launch_bounds__(256) void k_scatter(const void* __restrict__ ei) {
    int base = blockIdx.x * 1024 + threadIdx.x;
    #pragma unroll
    for (int j = 0; j < 4; j++) {
        int e = base + j * 256;
        if (e < ETOT) {
            int src, dst;
            load_edge(ei, e, src, dst);
            int pos = atomicAdd(&g_cursor[dst], 1);
            g_esrc[pos] = src;
        }
    }
}

// FUSED edge pass: warp per node, TWO edges per iteration (16 lanes each,
// 8 channels per lane). Fixed-baseline softmax, fused GraphNorm stats.
__global__ __launch_bounds__(256) void k_edge(const float* __restrict__ att,
                                              const float* __restrict__ bias,
                                              float* __restrict__ out) {
    __shared__ float ss1[HC], ss2[HC];
    int t = threadIdx.x;
    if (t < HC) { ss1[t] = 0.0f; ss2[t] = 0.0f; }
    __syncthreads();

    int n = (blockIdx.x * blockDim.x + t) >> 5;
    int lane = t & 31;
    int half = lane >> 4;        // 0: even edges, 1: odd edges
    int c4 = lane & 15;          // 8-channel group [c4*8, c4*8+8)

    if (n < NN) {
        int base = g_off[n];
        int deg = g_off[n + 1] - base;   // >= 1 (self-loop)
        const int* ep = g_esrc + base;

        float b[8], w[8];
        {
            float4 v = *(const float4*)(g_xr + (size_t)n * HC + c4 * 8);
            b[0] = v.x; b[1] = v.y; b[2] = v.z; b[3] = v.w;
            v = *(const float4*)(g_xr + (size_t)n * HC + c4 * 8 + 4);
            b[4] = v.x; b[5] = v.y; b[6] = v.z; b[7] = v.w;
            v = *(const float4*)(att + c4 * 8);
            w[0] = v.x; w[1] = v.y; w[2] = v.z; w[3] = v.w;
            v = *(const float4*)(att + c4 * 8 + 4);
            w[4] = v.x; w[5] = v.y; w[6] = v.z; w[7] = v.w;
        }

        float acc[8];
        #pragma unroll
        for (int j = 0; j < 8; j++) acc[j] = 0.0f;
        float s = 0.0f, p0 = 0.0f;

        const uint4* XL4 = (const uint4*)g_xlh;   // 16 uint4 per node row
        // lane's edge in pair i is (i + half); clamp index for safe loads
        int ec0 = min(half, deg - 1);
        int ec1 = min(2 + half, deg - 1);
        uint4 rc = XL4[(size_t)ep[ec0] * 16 + c4];
        uint4 rn = XL4[(size_t)ep[ec1] * 16 + c4];

        for (int i = 0; i < deg; i += 2) {
            int ecf = min(i + 4 + half, deg - 1);
            uint4 rf = XL4[(size_t)ep[ecf] * 16 + c4];

            float f[8];
            {
                float2 h;
                h = __half22float2(*(__half2*)&rc.x); f[0] = h.x; f[1] = h.y;
                h = __half22float2(*(__half2*)&rc.y); f[2] = h.x; f[3] = h.y;
                h = __half22float2(*(__half2*)&rc.z); f[4] = h.x; f[5] = h.y;
                h = __half22float2(*(__half2*)&rc.w); f[6] = h.x; f[7] = h.y;
            }
            float p = 0.0f;
            #pragma unroll
            for (int j = 0; j < 8; j++) {
                float v = f[j] + b[j];
                v = (v > 0.f) ? v : NEG * v;
                p += v * w[j];
            }
            // reduce over the 8 lanes of this (edge, head) group
            p += __shfl_xor_sync(0xffffffffu, p, 1);
            p += __shfl_xor_sync(0xffffffffu, p, 2);
            p += __shfl_xor_sync(0xffffffffu, p, 4);

            if (i == 0) p0 = __shfl_sync(0xffffffffu, p, c4 & 8); // edge0, own head
            bool valid = (i + half) < deg;
            float e2 = valid ? __expf(p - p0) : 0.0f;
            s += e2;
            #pragma unroll
            for (int j = 0; j < 8; j++) acc[j] += e2 * f[j];

            rc = rn; rn = rf;
        }
        // merge the two edge-halves (same channels in lane and lane^16)
        s += __shfl_xor_sync(0xffffffffu, s, 16);
        #pragma unroll
        for (int j = 0; j < 8; j++)
            acc[j] += __shfl_xor_sync(0xffffffffu, acc[j], 16);

        if (half == 0) {
            float si = 1.0f / s;
            float o[8];
            float4 bi = *(const float4*)(bias + c4 * 8);
            o[0] = acc[0] * si + bi.x; o[1] = acc[1] * si + bi.y;
            o[2] = acc[2] * si + bi.z; o[3] = acc[3] * si + bi.w;
            bi = *(const float4*)(bias + c4 * 8 + 4);
            o[4] = acc[4] * si + bi.x; o[5] = acc[5] * si + bi.y;
            o[6] = acc[6] * si + bi.z; o[7] = acc[7] * si + bi.w;

            *(float4*)(out + (size_t)n * HC + c4 * 8)     = make_float4(o[0], o[1], o[2], o[3]);
            *(float4*)(out + (size_t)n * HC + c4 * 8 + 4) = make_float4(o[4], o[5], o[6], o[7]);

            #pragma unroll
            for (int j = 0; j < 8; j++) {
                int c = c4 * 8 + j;
                atomicAdd(&ss1[c], o[j]);
                atomicAdd(&ss2[c], o[j] * o[j]);
            }
        }
    }
    __syncthreads();
    if (t < HC) {
        atomicAdd(&g_chs1[t], ss1[t]);
        atomicAdd(&g_chs2[t], ss2[t]);
    }
}

// precompute per-channel affine (scale, shift) — removes per-element rsqrt
__global__ void k_nprep(const float* __restrict__ gw,
                        const float* __restrict__ gb,
                        const float* __restrict__ gms) {
    int c = threadIdx.x;
    const float invn = 1.0f / (float)NN;
    float mean = g_chs1[c] * invn;
    float m2   = g_chs2[c] * invn;
    float ms   = mean * gms[c];
    float var  = m2 - 2.0f * ms * mean + ms * ms;
    float sc   = gw[c] * rsqrtf(var + EPSV);
    g_nsc[c] = sc;
    g_nsh[c] = gb[c] - sc * ms;
}

// norm: pure FFMA, in place
__global__ __launch_bounds__(256) void k_norm(float* __restrict__ out) {
    size_t stride = (size_t)gridDim.x * blockDim.x;   // multiple of 32
    size_t i0 = (size_t)blockIdx.x * blockDim.x + threadIdx.x;
    int c4 = (int)(i0 & 31);
    float4 sc0 = *(const float4*)(g_nsc + c4 * 4);
    float4 sh0 = *(const float4*)(g_nsh + c4 * 4);
    float4* o4 = (float4*)out;
    for (size_t i = i0; i < (size_t)NN * 32; i += stride) {
        float4 v = o4[i];
        v.x = v.x * sc0.x + sh0.x;
        v.y = v.y * sc0.y + sh0.y;
        v.z = v.z * sc0.z + sh0.z;
        v.w = v.w * sc0.w + sh0.w;
        o4[i] = v;
    }
}

// ---------------- launch ------------------------------------------------------
extern "C" void kernel_launch(void* const* d_in, const int* in_sizes, int n_in,
                              void* d_out, int out_size) {
    const float* x    = (const float*)d_in[0];
    const void*  ei   = d_in[1];
    const float* Wl   = (const float*)d_in[2];
    const float* Wr   = (const float*)d_in[3];
    const float* att  = (const float*)d_in[4];
    const float* bias = (const float*)d_in[5];
    const float* gw   = (const float*)d_in[6];
    const float* gb   = (const float*)d_in[7];
    const float* gms  = (const float*)d_in[8];
    float* out = (float*)d_out;

    k_detect<<<1, 32>>>(ei);
    k_zero<<<(NN + 255) / 256, 256>>>();
    k_gemm<<<GEMM_BLOCKS, 128>>>(x, Wl, Wr, ei);   // gemm + fused histogram

    k_scan1<<<SCAN_BLOCKS, 256>>>();
    k_scan2<<<1, 256>>>();
    k_scan3<<<SCAN_BLOCKS, 256>>>();

    int eblk4 = (ETOT + 1023) / 1024;
    k_scatter<<<eblk4, 256>>>(ei);

    int nblk = (NN * 32 + 255) / 256;  // warp per node
    k_edge<<<nblk, 256>>>(att, bias, out);

    k_nprep<<<1, HC>>>(gw, gb, gms);
    k_norm<<<2048, 256>>>(out);
}

// round 17
// speedup vs baseline: 1.0620x; 1.0620x over previous
#include <cuda_runtime.h>
#include <cuda_fp16.h>
#include <cstdint>
#include <math_constants.h>

#define NN   50000
#define EE   1600000
#define ETOT (EE + NN)
#define HC   128
#define NH   2
#define NEG  0.2f
#define EPSV 1e-5f

#define GEMM_BLOCKS ((NN + 63) / 64)    // 782
#define SCAN_BLOCKS ((NN + 255) / 256)  // 196

// ---------------- scratch (device globals; no runtime allocation) ----------
__device__ __half2  g_xlh[(size_t)NN * 64];     // x @ W_l in fp16 (12.8 MB)
__device__ float    g_xr[(size_t)NN * HC];      // x @ W_r   (25.6 MB)
__device__ int      g_esrc[ETOT];               // CSR src array (6.6 MB)
__device__ int      g_deg[NN];
__device__ int      g_off[NN + 1];
__device__ int      g_cursor[NN];
__device__ int      g_bsum[SCAN_BLOCKS];
__device__ int      g_bsumx[SCAN_BLOCKS];
__device__ float    g_chs1[HC];
__device__ float    g_chs2[HC];
__device__ float    g_nsc[HC];                  // norm scale
__device__ float    g_nsh[HC];                  // norm shift
__device__ int      g_is64;

// ---------------- helpers ---------------------------------------------------
__device__ __forceinline__ void load_edge(const void* ei, int e, int& src, int& dst) {
    if (e >= EE) { src = dst = e - EE; return; }
    if (g_is64) {
        const long long* p = (const long long*)ei;
        src = (int)p[e]; dst = (int)p[EE + e];
    } else {
        const int* p = (const int*)ei;
        src = p[e]; dst = p[EE + e];
    }
}

__device__ __forceinline__ void tf32split(float v, uint32_t& hi, uint32_t& lo) {
    uint32_t h;
    asm("cvt.rna.tf32.f32 %0, %1;" : "=r"(h) : "f"(v));
    float l = v - __uint_as_float(h);
    uint32_t lr;
    asm("cvt.rna.tf32.f32 %0, %1;" : "=r"(lr) : "f"(l));
    hi = h; lo = lr;
}

__device__ __forceinline__ void mma8(float c[4], uint32_t a0, uint32_t a1,
                                     uint32_t a2, uint32_t a3,
                                     uint32_t b0, uint32_t b1) {
    asm volatile(
        "mma.sync.aligned.m16n8k8.row.col.f32.tf32.tf32.f32 "
        "{%0,%1,%2,%3}, {%4,%5,%6,%7}, {%8,%9}, {%0,%1,%2,%3};"
        : "+f"(c[0]), "+f"(c[1]), "+f"(c[2]), "+f"(c[3])
        : "r"(a0), "r"(a1), "r"(a2), "r"(a3), "r"(b0), "r"(b1));
}

__device__ __forceinline__ int block_scan_incl(int v, int t) {
    __shared__ int sw[8];
    int lane = t & 31, warp = t >> 5;
    #pragma unroll
    for (int off = 1; off < 32; off <<= 1) {
        int u = __shfl_up_sync(0xffffffffu, v, off);
        if (lane >= off) v += u;
    }
    if (lane == 31) sw[warp] = v;
    __syncthreads();
    if (warp == 0) {
        int wv = (lane < 8) ? sw[lane] : 0;
        #pragma unroll
        for (int off = 1; off < 8; off <<= 1) {
            int u = __shfl_up_sync(0xffffffffu, wv, off);
            if (lane >= off) wv += u;
        }
        if (lane < 8) sw[lane] = wv;
    }
    __syncthreads();
    if (warp > 0) v += sw[warp - 1];
    return v;
}

// ---------------- kernels ----------------------------------------------------

__global__ void k_detect(const void* ei) {
    if (threadIdx.x == 0) {
        const int* p = (const int*)ei;
        int is64 = 1;
        #pragma unroll 1
        for (int i = 0; i < 64; i++)
            if (p[2 * i + 1] != 0) { is64 = 0; break; }
        g_is64 = is64;
    }
}

__global__ void k_zero(void) {
    int i = blockIdx.x * blockDim.x + threadIdx.x;
    if (i < NN) g_deg[i] = 0;
    if (i < HC) { g_chs1[i] = 0.0f; g_chs2[i] = 0.0f; }
}

// Tensor-core GEMM (3xTF32 split) with fused degree histogram tail.
// (round-14 version: B split in inner loop, smem 42 KB)
__global__ __launch_bounds__(128) void k_gemm(const float* __restrict__ x,
                                              const float* __restrict__ Wl,
                                              const float* __restrict__ Wr,
                                              const void* __restrict__ ei) {
    __shared__ float xs[64][132];
    __shared__ float ws[16][132];
    const int node0 = blockIdx.x * 64;
    const int t = threadIdx.x;
    const int warp = t >> 5, lane = t & 31;
    const int gid = lane >> 2, tig = lane & 3;
    const int m0 = warp * 16;

    const float4* x4 = (const float4*)x;
    #pragma unroll
    for (int i = 0; i < 16; i++) {
        int lin = t + i * 128;
        int row = lin >> 5, c4 = lin & 31;
        int node = node0 + row;
        float4 v = (node < NN) ? x4[(size_t)node * 32 + c4]
                               : make_float4(0.f, 0.f, 0.f, 0.f);
        *(float4*)&xs[row][c4 * 4] = v;
    }

    const float* Wmat[2] = { Wl, Wr };

    #pragma unroll 1
    for (int g = 0; g < 2; g++) {
        const float* W = Wmat[g];
        float c[16][4];
        #pragma unroll
        for (int nt = 0; nt < 16; nt++)
            c[nt][0] = c[nt][1] = c[nt][2] = c[nt][3] = 0.0f;

        #pragma unroll 1
        for (int kc = 0; kc < 128; kc += 16) {
            __syncthreads();
            #pragma unroll
            for (int i = 0; i < 4; i++) {
                int lin = t + i * 128;
                int row = lin >> 5, c4 = lin & 31;
                *(float4*)&ws[row][c4 * 4] =
                    *(const float4*)&W[(size_t)(kc + row) * 128 + c4 * 4];
            }
            __syncthreads();

            #pragma unroll
            for (int ks = 0; ks < 2; ks++) {
                int kk = ks * 8;
                float a0 = xs[m0 + gid][kc + kk + tig];
                float a1 = xs[m0 + gid + 8][kc + kk + tig];
                float a2 = xs[m0 + gid][kc + kk + tig + 4];
                float a3 = xs[m0 + gid + 8][kc + kk + tig + 4];
                uint32_t ah0, al0, ah1, al1, ah2, al2, ah3, al3;
                tf32split(a0, ah0, al0);
                tf32split(a1, ah1, al1);
                tf32split(a2, ah2, al2);
                tf32split(a3, ah3, al3);
                #pragma unroll
                for (int nt = 0; nt < 16; nt++) {
                    int n0 = nt * 8;
                    float b0 = ws[kk + tig][n0 + gid];
                    float b1 = ws[kk + tig + 4][n0 + gid];
                    uint32_t bh0, bl0, bh1, bl1;
                    tf32split(b0, bh0, bl0);
                    tf32split(b1, bh1, bl1);
                    mma8(c[nt], ah0, ah1, ah2, ah3, bh0, bh1);
                    mma8(c[nt], ah0, ah1, ah2, ah3, bl0, bl1);
                    mma8(c[nt], al0, al1, al2, al3, bh0, bh1);
                }
            }
        }
        int r0 = node0 + m0 + gid;
        int r1 = r0 + 8;
        if (g == 0) {
            #pragma unroll
            for (int nt = 0; nt < 16; nt++) {
                int h2 = (nt * 8 + tig * 2) >> 1;
                if (r0 < NN) g_xlh[(size_t)r0 * 64 + h2] = __floats2half2_rn(c[nt][0], c[nt][1]);
                if (r1 < NN) g_xlh[(size_t)r1 * 64 + h2] = __floats2half2_rn(c[nt][2], c[nt][3]);
            }
        } else {
            #pragma unroll
            for (int nt = 0; nt < 16; nt++) {
                int col = nt * 8 + tig * 2;
                if (r0 < NN) *(float2*)&g_xr[(size_t)r0 * HC + col] = make_float2(c[nt][0], c[nt][1]);
                if (r1 < NN) *(float2*)&g_xr[(size_t)r1 * HC + col] = make_float2(c[nt][2], c[nt][3]);
            }
        }
        __syncthreads();
    }

    // ---- fused degree histogram tail ----
    const int EPB = (ETOT + GEMM_BLOCKS - 1) / GEMM_BLOCKS;
    int e0 = blockIdx.x * EPB;
    int e1 = min(e0 + EPB, ETOT);
    for (int e = e0 + t; e < e1; e += 128) {
        int src, dst;
        load_edge(ei, e, src, dst);
        (void)src;
        atomicAdd(&g_deg[dst], 1);
    }
}

// scan phase 1/2/3: device-wide exclusive scan of degrees
__global__ __launch_bounds__(256) void k_scan1(void) {
    int i = blockIdx.x * 256 + threadIdx.x;
    int d = (i < NN) ? g_deg[i] : 0;
    int incl = block_scan_incl(d, threadIdx.x);
    if (threadIdx.x == 255) g_bsum[blockIdx.x] = incl;
    g_off[min(i, NN)] = incl - d;
}
__global__ __launch_bounds__(256) void k_scan2(void) {
    int t = threadIdx.x;
    int v = (t < SCAN_BLOCKS) ? g_bsum[t] : 0;
    int incl = block_scan_incl(v, t);
    if (t < SCAN_BLOCKS) g_bsumx[t] = incl - v;
    if (t == SCAN_BLOCKS - 1) g_off[NN] = incl;
}
__global__ __launch_bounds__(256) void k_scan3(void) {
    int i = blockIdx.x * 256 + threadIdx.x;
    if (i < NN) {
        int o = g_off[i] + g_bsumx[blockIdx.x];
        g_off[i] = o;
        g_cursor[i] = o;
    }
}

// CSR scatter: srcs grouped by dst (4 edges/thread)
__global__ __launch_bounds__(256) void k_scatter(const void* __restrict__ ei) {
    int base = blockIdx.x * 1024 + threadIdx.x;
    #pragma unroll
    for (int j = 0; j < 4; j++) {
        int e = base + j * 256;
        if (e < ETOT) {
            int src, dst;
            load_edge(ei, e, src, dst);
            int pos = atomicAdd(&g_cursor[dst], 1);
            g_esrc[pos] = src;
        }
    }
}

// FUSED edge pass (round-14 version): warp per node, fixed-baseline softmax,
// fp16 gather, 2-deep prefetch, fused GraphNorm stats.
__global__ __launch_bounds__(256) void k_edge(const float* __restrict__ att,
                                              const float* __restrict__ bias,
                                              float* __restrict__ out) {
    __shared__ float ss1[HC], ss2[HC];
    int t = threadIdx.x;
    if (t < HC) { ss1[t] = 0.0f; ss2[t] = 0.0f; }
    __syncthreads();

    int n = (blockIdx.x * blockDim.x + t) >> 5;
    int lane = t & 31;

    if (n < NN) {
        int base = g_off[n];
        int deg = g_off[n + 1] - base;   // >= 1 (self-loop)
        const int* ep = g_esrc + base;

        float4 b = *(const float4*)(g_xr + (size_t)n * HC + lane * 4);
        float4 w = *(const float4*)(att + lane * 4);

        float s = 0.0f, p0 = 0.0f;
        float4 acc = make_float4(0.f, 0.f, 0.f, 0.f);

        const __half2* XL = g_xlh;
        int s0 = ep[0];
        int s1 = (deg > 1) ? ep[1] : s0;
        uint2 r0 = *(const uint2*)(XL + (size_t)s0 * 64 + lane * 2);
        uint2 r1 = *(const uint2*)(XL + (size_t)s1 * 64 + lane * 2);

        #pragma unroll 2
        for (int i = 0; i < deg; i++) {
            int s2 = (i + 2 < deg) ? ep[i + 2] : 0;
            uint2 r2 = *(const uint2*)(XL + (size_t)s2 * 64 + lane * 2);

            float2 alo = __half22float2(*(__half2*)&r0.x);
            float2 ahi = __half22float2(*(__half2*)&r0.y);

            float sx = alo.x + b.x, sy = alo.y + b.y, sz = ahi.x + b.z, sw = ahi.y + b.w;
            sx = (sx > 0.f) ? sx : NEG * sx;
            sy = (sy > 0.f) ? sy : NEG * sy;
            sz = (sz > 0.f) ? sz : NEG * sz;
            sw = (sw > 0.f) ? sw : NEG * sw;
            float p = sx * w.x + sy * w.y + sz * w.z + sw * w.w;
            p += __shfl_xor_sync(0xffffffffu, p, 1);
            p += __shfl_xor_sync(0xffffffffu, p, 2);
            p += __shfl_xor_sync(0xffffffffu, p, 4);
            p += __shfl_xor_sync(0xffffffffu, p, 8);

            if (i == 0) p0 = p;          // fixed baseline
            float e2 = __expf(p - p0);
            s += e2;
            acc.x += e2 * alo.x;
            acc.y += e2 * alo.y;
            acc.z += e2 * ahi.x;
            acc.w += e2 * ahi.y;
            r0 = r1; r1 = r2;
        }
        float si = 1.0f / s;
        float4 bi = *(const float4*)(bias + lane * 4);
        float4 o = make_float4(acc.x * si + bi.x, acc.y * si + bi.y,
                               acc.z * si + bi.z, acc.w * si + bi.w);
        *(float4*)(out + (size_t)n * HC + lane * 4) = o;

        int c = lane * 4;
        atomicAdd(&ss1[c + 0], o.x); atomicAdd(&ss2[c + 0], o.x * o.x);
        atomicAdd(&ss1[c + 1], o.y); atomicAdd(&ss2[c + 1], o.y * o.y);
        atomicAdd(&ss1[c + 2], o.z); atomicAdd(&ss2[c + 2], o.z * o.z);
        atomicAdd(&ss1[c + 3], o.w); atomicAdd(&ss2[c + 3], o.w * o.w);
    }
    __syncthreads();
    if (t < HC) {
        atomicAdd(&g_chs1[t], ss1[t]);
        atomicAdd(&g_chs2[t], ss2[t]);
    }
}

// precompute per-channel affine (scale, shift) — removes per-element rsqrt
__global__ void k_nprep(const float* __restrict__ gw,
                        const float* __restrict__ gb,
                        const float* __restrict__ gms) {
    int c = threadIdx.x;
    const float invn = 1.0f / (float)NN;
    float mean = g_chs1[c] * invn;
    float m2   = g_chs2[c] * invn;
    float ms   = mean * gms[c];
    float var  = m2 - 2.0f * ms * mean + ms * ms;
    float sc   = gw[c] * rsqrtf(var + EPSV);
    g_nsc[c] = sc;
    g_nsh[c] = gb[c] - sc * ms;
}

// norm: pure FFMA, in place
__global__ __launch_bounds__(256) void k_norm(float* __restrict__ out) {
    size_t stride = (size_t)gridDim.x * blockDim.x;   // multiple of 32
    size_t i0 = (size_t)blockIdx.x * blockDim.x + threadIdx.x;
    int c4 = (int)(i0 & 31);
    float4 sc0 = *(const float4*)(g_nsc + c4 * 4);
    float4 sh0 = *(const float4*)(g_nsh + c4 * 4);
    float4* o4 = (float4*)out;
    for (size_t i = i0; i < (size_t)NN * 32; i += stride) {
        float4 v = o4[i];
        v.x = v.x * sc0.x + sh0.x;
        v.y = v.y * sc0.y + sh0.y;
        v.z = v.z * sc0.z + sh0.z;
        v.w = v.w * sc0.w + sh0.w;
        o4[i] = v;
    }
}

// ---------------- launch ------------------------------------------------------
extern "C" void kernel_launch(void* const* d_in, const int* in_sizes, int n_in,
                              void* d_out, int out_size) {
    const float* x    = (const float*)d_in[0];
    const void*  ei   = d_in[1];
    const float* Wl   = (const float*)d_in[2];
    const float* Wr   = (const float*)d_in[3];
    const float* att  = (const float*)d_in[4];
    const float* bias = (const float*)d_in[5];
    const float* gw   = (const float*)d_in[6];
    const float* gb   = (const float*)d_in[7];
    const float* gms  = (const float*)d_in[8];
    float* out = (float*)d_out;

    k_detect<<<1, 32>>>(ei);
    k_zero<<<(NN + 255) / 256, 256>>>();
    k_gemm<<<GEMM_BLOCKS, 128>>>(x, Wl, Wr, ei);   // gemm + fused histogram

    k_scan1<<<SCAN_BLOCKS, 256>>>();
    k_scan2<<<1, 256>>>();
    k_scan3<<<SCAN_BLOCKS, 256>>>();

    int eblk4 = (ETOT + 1023) / 1024;
    k_scatter<<<eblk4, 256>>>(ei);

    int nblk = (NN * 32 + 255) / 256;  // warp per node
    k_edge<<<nblk, 256>>>(att, bias, out);

    k_nprep<<<1, HC>>>(gw, gb, gms);
    k_norm<<<2048, 256>>>(out);
}